// round 11
// baseline (speedup 1.0000x reference)
#include <cuda_runtime.h>
#include <cstdint>

// DigitCaps broadcasted batched matvec:
//   u_hat[b,r,c,o] = sum_i W[r,c,o,i] * x[b,r,i] + bias[o]
// B=512, R=1152, C=10, O=16, I=8, fp32.
//
// R9: TMA bulk stores. R8 (68.2us) was L1-bound at 82.7% with STG.128 issue
// the dominant term (737K warp-instrs x 12+ cyc, 4 scattered 128B segments
// each). Output per (block,b) is CONTIGUOUS (out[b, r0:r0+RB, :, :] =
// RB*640B), so: compute exactly as R8 (x in regs via uniform LDG.128, W in
// padded conflict-free smem), write results to a smem stage via STS.128
// (~4cyc crossbar), then one thread flushes 16 contiguous 1280B runs with
// cp.async.bulk.shared->global (TMA engine; no per-warp LSU cost).
// RB=2, block=64: stage 20KB + W 11.5KB = 31.5KB -> 7 CTAs = 14 warps/SM.
// Lane = bg(4) x c2(2) x o4(4); warp w = r_local. 4 b's x 2 c's x 4 o's/thread.

#define DC_B 512
#define DC_R 1152
#define DC_C 10
#define DC_O 16
#define DC_I 8

#define RB 2     // r rows per block (one per warp)
#define BT 16    // batch elems per block

#define SW_FLOATS 2880              // 2r * 10c * 4(o4) rows of 36 floats
#define SO_FLOATS (BT * RB * 160)   // 5120 floats = 20480 B stage
#define SMEM_BYTES ((SW_FLOATS + SO_FLOATS) * 4)
#define CHUNK_BYTES (RB * 160 * 4)  // 1280 B contiguous per b

__global__ __launch_bounds__(64, 7)
void digitcaps_kernel(const float* __restrict__ x,
                      const float* __restrict__ W,
                      const float* __restrict__ bias,
                      float* __restrict__ out)
{
    extern __shared__ float smem[];
    float* sW = smem;               // [g][36], g = (r_local*10 + c)*4 + o4
    float* sO = smem + SW_FLOATS;   // [b_local][r_local][160]

    const int tid = threadIdx.x;
    const int r0  = blockIdx.x * RB;
    const int b0  = blockIdx.y * BT;

    // ---- cooperative W load: 2 r rows * 1280 floats = 640 float4, coalesced ----
    {
        const float4* Wg = reinterpret_cast<const float4*>(
            W + (size_t)r0 * (DC_C * DC_O * DC_I));
#pragma unroll
        for (int q4 = 0; q4 < 10; ++q4) {
            const int q = q4 * 64 + tid;            // float4 index in W tile
            const float4 v = Wg[q];
            // q -> (rc, o, ih): flat = ((rc)*16 + o)*2 + ih
            const int ih = q & 1;
            const int o  = (q >> 1) & 15;
            const int rc = q >> 5;                   // r_local*10 + c
            const int g  = rc * 4 + (o >> 2);
            *reinterpret_cast<float4*>(sW + g * 36 + (o & 3) * 8 + ih * 4) = v;
        }
    }

    const int lane = tid & 31;
    const int w    = tid >> 5;       // warp id == r_local (0..1)
    const int bg   = lane >> 3;      // 0..3 batch group
    const int c2   = (lane >> 2) & 1;
    const int o4   = lane & 3;

    const int r = r0 + w;

    // ---- x in registers: this thread's 4 b's (bl = k*4+bg), 8 floats each.
    //      Address uniform across the 8 lanes sharing bg -> broadcast LDG. ----
    float4 xa[4], xb[4];
#pragma unroll
    for (int k = 0; k < 4; ++k) {
        const int bl = k * 4 + bg;
        const float4* xp = reinterpret_cast<const float4*>(
            x + ((size_t)(b0 + bl) * DC_R + r) * DC_I);
        xa[k] = xp[0];
        xb[k] = xp[1];
    }

    const float4 bb = *reinterpret_cast<const float4*>(bias + o4 * 4);

    __syncthreads();

#pragma unroll
    for (int cp = 0; cp < 5; ++cp) {
        const int c = cp * 2 + c2;
        // W row for (r, c, o4): 32 floats. 8 distinct padded rows per warp,
        // stride 36 floats -> conflict-free; bg broadcast dedups.
        const float* wr = sW + ((w * DC_C + c) * 4 + o4) * 36;
        const float4 w0a = *reinterpret_cast<const float4*>(wr + 0);
        const float4 w0b = *reinterpret_cast<const float4*>(wr + 4);
        const float4 w1a = *reinterpret_cast<const float4*>(wr + 8);
        const float4 w1b = *reinterpret_cast<const float4*>(wr + 12);
        const float4 w2a = *reinterpret_cast<const float4*>(wr + 16);
        const float4 w2b = *reinterpret_cast<const float4*>(wr + 20);
        const float4 w3a = *reinterpret_cast<const float4*>(wr + 24);
        const float4 w3b = *reinterpret_cast<const float4*>(wr + 28);

#pragma unroll
        for (int k = 0; k < 4; ++k) {
            const float4 va = xa[k];
            const float4 vb = xb[k];

            float4 acc;
            acc.x = fmaf(w0a.x, va.x, fmaf(w0a.y, va.y,
                    fmaf(w0a.z, va.z, fmaf(w0a.w, va.w,
                    fmaf(w0b.x, vb.x, fmaf(w0b.y, vb.y,
                    fmaf(w0b.z, vb.z, fmaf(w0b.w, vb.w, bb.x))))))));
            acc.y = fmaf(w1a.x, va.x, fmaf(w1a.y, va.y,
                    fmaf(w1a.z, va.z, fmaf(w1a.w, va.w,
                    fmaf(w1b.x, vb.x, fmaf(w1b.y, vb.y,
                    fmaf(w1b.z, vb.z, fmaf(w1b.w, vb.w, bb.y))))))));
            acc.z = fmaf(w2a.x, va.x, fmaf(w2a.y, va.y,
                    fmaf(w2a.z, va.z, fmaf(w2a.w, va.w,
                    fmaf(w2b.x, vb.x, fmaf(w2b.y, vb.y,
                    fmaf(w2b.z, vb.z, fmaf(w2b.w, vb.w, bb.z))))))));
            acc.w = fmaf(w3a.x, va.x, fmaf(w3a.y, va.y,
                    fmaf(w3a.z, va.z, fmaf(w3a.w, va.w,
                    fmaf(w3b.x, vb.x, fmaf(w3b.y, vb.y,
                    fmaf(w3b.z, vb.z, fmaf(w3b.w, vb.w, bb.w))))))));

            const int bl = k * 4 + bg;
            // STS.128 to stage: 4 x 128B segments per warp instr, cheap crossbar.
            float* sp = sO + bl * (RB * 160) + w * 160 + c * DC_O + o4 * 4;
            *reinterpret_cast<float4*>(sp) = acc;
        }
    }
    __syncthreads();

    // ---- one thread flushes 16 contiguous 1280B runs via TMA bulk copy ----
    if (tid == 0) {
        asm volatile("fence.proxy.async.shared::cta;" ::: "memory");
        const uint32_t sbase = (uint32_t)__cvta_generic_to_shared(sO);
#pragma unroll
        for (int bi = 0; bi < BT; ++bi) {
            float* dst = out + ((size_t)(b0 + bi) * DC_R + r0) * (DC_C * DC_O);
            asm volatile(
                "cp.async.bulk.global.shared::cta.bulk_group [%0], [%1], %2;"
                :: "l"(dst), "r"(sbase + bi * CHUNK_BYTES),
                   "r"((uint32_t)CHUNK_BYTES)
                : "memory");
        }
        asm volatile("cp.async.bulk.commit_group;" ::: "memory");
        asm volatile("cp.async.bulk.wait_group 0;" ::: "memory");
    }
    __syncthreads();   // smem must stay live until the bulk copies complete
}

extern "C" void kernel_launch(void* const* d_in, const int* in_sizes, int n_in,
                              void* d_out, int out_size)
{
    const float* x    = (const float*)d_in[0];  // [B, R, I]
    const float* W    = (const float*)d_in[1];  // [1, R, C, O, I]
    const float* bias = (const float*)d_in[2];  // [O, 1]
    float* out = (float*)d_out;                 // [B, R, C, O, 1]

    cudaFuncSetAttribute(digitcaps_kernel,
                         cudaFuncAttributeMaxDynamicSharedMemorySize, SMEM_BYTES);

    dim3 block(64, 1, 1);
    dim3 grid(DC_R / RB, DC_B / BT, 1);   // (576, 32)
    digitcaps_kernel<<<grid, block, SMEM_BYTES>>>(x, W, bias, out);
}